// round 2
// baseline (speedup 1.0000x reference)
#include <cuda_runtime.h>

#define NB 48
#define NL 17
#define ND 256
#define NM 768   /* NB*(NL-1) */

__device__ float g_toks[NM*ND];
__device__ float g_anch[NB*ND];
__device__ float g_Et  [NM*NM];   // exp(s_tok[j,k])
__device__ float g_Ea  [NB*NM];   // exp(s_anc[b,k])
__device__ float g_c   [NB];      // 1 / sum_neg exp(s_anc)  == exp(-log_denom)
__device__ float g_kl  [NB*NM];   // 0.5*(kl1+kl2) per (b,j)
__device__ float g_nneg[NB];
__device__ int   g_lab [NB];

// ---------------------------------------------------------------- utilities
__device__ __forceinline__ float blockReduceSum(float v, volatile float* sm) {
    int lane = threadIdx.x & 31, wid = threadIdx.x >> 5;
    #pragma unroll
    for (int o = 16; o > 0; o >>= 1) v += __shfl_down_sync(0xffffffffu, v, o);
    if (lane == 0) sm[wid] = v;
    __syncthreads();
    if (threadIdx.x < 32) {
        float r = (threadIdx.x < 8) ? sm[threadIdx.x] : 0.f;
        #pragma unroll
        for (int o = 4; o > 0; o >>= 1) r += __shfl_down_sync(0xffffffffu, r, o);
        if (threadIdx.x == 0) sm[0] = r;
    }
    __syncthreads();
    float r = sm[0];
    __syncthreads();
    return r;
}

// ------------------------------------------------- 0: label dtype detection
// Reference declares int64 labels; jax w/o x64 silently yields int32. An
// int64 buffer read as int32 (little-endian, values 0..7) is [v,0,v,0,...].
__global__ void k_labels(const int* __restrict__ lab32) {
    if (threadIdx.x != 0) return;
    bool is64 = true;
    for (int i = 1; i < NB; i += 2) if (lab32[i] != 0) { is64 = false; break; }
    if (is64) for (int i = 0; i < NB; i += 2) {
        int v = lab32[i];
        if (v < 0 || v >= 8) { is64 = false; break; }
    }
    if (is64) {
        const long long* l64 = (const long long*)lab32;
        for (int i = 0; i < NB; i++) g_lab[i] = (int)l64[i];
    } else {
        for (int i = 0; i < NB; i++) g_lab[i] = lab32[i];
    }
    for (int b = 0; b < NB; b++) {
        int n = 0;
        for (int o = 0; o < NB; o++) if (g_lab[o] != g_lab[b]) n += (NL - 1);
        g_nneg[b] = (float)n;
    }
}

// ------------------------------------------------------------ 1: normalize
__global__ void k_norm(const float* __restrict__ x) {
    __shared__ float red[32];
    int r = blockIdx.x, d = threadIdx.x;
    float v = x[r * ND + d];
    float ss = blockReduceSum(v * v, red);
    float inv = 1.f / fmaxf(sqrtf(ss), 1e-12f);
    float xn = v * inv;
    int b = r / NL, p = r - b * NL;
    if (p == 0) g_anch[b * ND + d] = xn;
    else        g_toks[(b * (NL - 1) + p - 1) * ND + d] = xn;
}

// -------------------------- 2: anchor sims -> Ea = exp(s_anc), c = 1/sum_neg
__global__ void k_anchor(void) {
    int b = blockIdx.x, t = threadIdx.x;
    __shared__ float anc[ND];
    __shared__ int   lab[NB];
    __shared__ float red[32];
    anc[t] = g_anch[b * ND + t];
    if (t < NB) lab[t] = g_lab[t];
    __syncthreads();
    int mb = lab[b];

    float E[3]; float p = 0.f;
    const float4* an = (const float4*)anc;
    #pragma unroll
    for (int q = 0; q < 3; q++) {
        int k = t + q * 256;
        const float4* tk = (const float4*)(g_toks + k * ND);
        float dot = 0.f;
        #pragma unroll 8
        for (int d = 0; d < ND / 4; d++) {
            float4 a = an[d], v = tk[d];
            dot += a.x * v.x + a.y * v.y + a.z * v.z + a.w * v.w;
        }
        E[q] = expf(dot);          // T = 1
        if (lab[k >> 4] != mb) p += E[q];
    }
    float P = blockReduceSum(p, red);
    #pragma unroll
    for (int q = 0; q < 3; q++) g_Ea[b * NM + t + q * 256] = E[q];
    if (t == 0) g_c[b] = 1.f / P;
}

// ------------------------------------- 3a: Et = exp(toks @ toks^T)  (fp32)
__global__ void k_gemm(void) {
    __shared__ float As[64][33];
    __shared__ float Bs[64][33];
    int tx = threadIdx.x & 15, ty = threadIdx.x >> 4;
    int jb = blockIdx.y * 64, kb = blockIdx.x * 64;
    float acc[4][4] = {};
    for (int k0 = 0; k0 < ND; k0 += 32) {
        for (int i = threadIdx.x; i < 64 * 32; i += 256) {
            int r = i >> 5, c = i & 31;
            As[r][c] = g_toks[(jb + r) * ND + k0 + c];
            Bs[r][c] = g_toks[(kb + r) * ND + k0 + c];
        }
        __syncthreads();
        #pragma unroll
        for (int dd = 0; dd < 32; dd++) {
            float a0 = As[ty*4+0][dd], a1 = As[ty*4+1][dd],
                  a2 = As[ty*4+2][dd], a3 = As[ty*4+3][dd];
            float b0 = Bs[tx*4+0][dd], b1 = Bs[tx*4+1][dd],
                  b2 = Bs[tx*4+2][dd], b3 = Bs[tx*4+3][dd];
            acc[0][0] += a0*b0; acc[0][1] += a0*b1; acc[0][2] += a0*b2; acc[0][3] += a0*b3;
            acc[1][0] += a1*b0; acc[1][1] += a1*b1; acc[1][2] += a1*b2; acc[1][3] += a1*b3;
            acc[2][0] += a2*b0; acc[2][1] += a2*b1; acc[2][2] += a2*b2; acc[2][3] += a2*b3;
            acc[3][0] += a3*b0; acc[3][1] += a3*b1; acc[3][2] += a3*b2; acc[3][3] += a3*b3;
        }
        __syncthreads();
    }
    #pragma unroll
    for (int i = 0; i < 4; i++)
        #pragma unroll
        for (int l = 0; l < 4; l++)
            g_Et[(jb + ty*4 + i) * NM + kb + tx*4 + l] = expf(acc[i][l]);
}

// ------------------- 3b: per-(b,j) symmetric KL, cancellation-free algebra
// e=c*Et, a=c*Ea, t=e-a, mu=exp(e)-1 (series), d=mu-nu=t*h (series)
// symKL = 0.5*(Sdt*D1 - Sd*N1)/(D1*D2); D1=n+Smu, N1=St+Smut, D2=D1-Sd
__global__ void k_pairs(void) {
    int j = blockIdx.x, b = blockIdx.y, t = threadIdx.x;
    __shared__ int lab[NB];
    __shared__ float red[8][5];
    if (t < NB) lab[t] = g_lab[t];
    __syncthreads();
    int mb = lab[b];
    if (lab[j >> 4] != mb) {              // row mask: pair unused
        if (t == 0) g_kl[b * NM + j] = 0.f;
        return;
    }
    float c = g_c[b];
    const float* Et = g_Et + j * NM;
    const float* Ea = g_Ea + b * NM;

    float s[5] = {0.f, 0.f, 0.f, 0.f, 0.f};   // St, Smu, Smut, Sd, Sdt
    #pragma unroll
    for (int q = 0; q < 3; q++) {
        int k = t + q * 256;
        if (lab[k >> 4] == mb) continue;       // neg mask over k
        float e  = c * Et[k];
        float a  = c * Ea[k];
        float tt = e - a;
        float mu = e * (1.f + e * (0.5f + e * (1.f/6.f + e * (1.f/24.f))));
        float sp = e + a;
        float h  = 1.f + 0.5f * sp
                 + (e*e + e*a + a*a) * (1.f/6.f)
                 + sp * (e*e + a*a) * (1.f/24.f);
        float d  = tt * h;
        s[0] += tt; s[1] += mu; s[2] += mu * tt; s[3] += d; s[4] += tt * d;
    }
    int lane = t & 31, wid = t >> 5;
    #pragma unroll
    for (int i = 0; i < 5; i++) {
        #pragma unroll
        for (int o = 16; o > 0; o >>= 1) s[i] += __shfl_down_sync(0xffffffffu, s[i], o);
    }
    if (lane == 0) {
        #pragma unroll
        for (int i = 0; i < 5; i++) red[wid][i] = s[i];
    }
    __syncthreads();
    if (t == 0) {
        float St = 0.f, Smu = 0.f, Smut = 0.f, Sd = 0.f, Sdt = 0.f;
        #pragma unroll
        for (int w = 0; w < 8; w++) {
            St += red[w][0]; Smu += red[w][1]; Smut += red[w][2];
            Sd += red[w][3]; Sdt += red[w][4];
        }
        float n  = g_nneg[b];
        float D1 = n + Smu;
        float N1 = St + Smut;
        float D2 = D1 - Sd;
        float num = Sdt * D1 - Sd * N1;
        g_kl[b * NM + j] = 0.5f * num / (D1 * D2);
    }
}

// -------------------------------------------- 4: deterministic final reduce
__global__ void k_final(float* __restrict__ out) {
    int t = threadIdx.x;
    __shared__ int lab[NB];
    __shared__ float red[32];
    __shared__ float acc;
    if (t < NB) lab[t] = g_lab[t];
    if (t == 0) acc = 0.f;
    __syncthreads();
    for (int b = 0; b < NB; b++) {
        int mb = lab[b];
        float rs = 0.f, cnt = 0.f;
        for (int j = t; j < NM; j += 256) {
            if (lab[j >> 4] == mb) { rs += g_kl[b * NM + j]; cnt += 1.f; }
        }
        float rowsum = blockReduceSum(rs, red);
        float P      = blockReduceSum(cnt, red);
        if (t == 0) acc += rowsum / P;
    }
    __syncthreads();
    if (t == 0) out[0] = acc / (float)NB;
}

// ----------------------------------------------------------------- launch
extern "C" void kernel_launch(void* const* d_in, const int* in_sizes, int n_in,
                              void* d_out, int out_size) {
    const float* x     = (const float*)d_in[0];
    const int*   lab32 = (const int*)  d_in[1];
    float*       out   = (float*)      d_out;
    (void)in_sizes; (void)n_in; (void)out_size;

    k_labels<<<1, 32>>>(lab32);
    k_norm  <<<NB * NL, 256>>>(x);
    k_anchor<<<NB, 256>>>();
    k_gemm  <<<dim3(NM / 64, NM / 64), 256>>>();
    k_pairs <<<dim3(NM, NB), 256>>>();
    k_final <<<1, 256>>>(out);
}

// round 3
// speedup vs baseline: 1.8684x; 1.8684x over previous
#include <cuda_runtime.h>

#define NB 48
#define NL 17
#define ND 256
#define NM 768   /* NB*(NL-1) */
#define KSPLIT 4
#define PAIR_BLOCKS 768

__device__ float g_toks[NM*ND];
__device__ float g_anch[NB*ND];
__device__ float g_sp  [KSPLIT][NM*NM]; // split-K partials of toks@toks^T
__device__ float g_Et  [NM*NM];         // exp(s_tok[j,k])
__device__ float g_Ea  [NB*NM];         // exp(s_anc[b,k])
__device__ float g_c   [NB];            // 1 / sum_neg exp(s_anc)
__device__ float g_kl  [NB*NM];         // symKL per (b,j), active pairs only
__device__ float g_row [NB];
__device__ float g_nneg[NB];
__device__ int   g_lab [NB];
__device__ int   g_base[NB];            // per-b offset into g_pairs
__device__ int   g_np;                  // total active pairs
__device__ int   g_pairs[NB*NM];        // (b<<16)|j, grouped by b, j-ascending

// ---------------------------------------------------------------- utilities
__device__ __forceinline__ float blockReduceSum(float v, volatile float* sm) {
    int lane = threadIdx.x & 31, wid = threadIdx.x >> 5;
    #pragma unroll
    for (int o = 16; o > 0; o >>= 1) v += __shfl_down_sync(0xffffffffu, v, o);
    if (lane == 0) sm[wid] = v;
    __syncthreads();
    if (threadIdx.x < 32) {
        float r = (threadIdx.x < 8) ? sm[threadIdx.x] : 0.f;
        #pragma unroll
        for (int o = 4; o > 0; o >>= 1) r += __shfl_down_sync(0xffffffffu, r, o);
        if (threadIdx.x == 0) sm[0] = r;
    }
    __syncthreads();
    float r = sm[0];
    __syncthreads();
    return r;
}

// --------------------------- 0: labels (dtype sniff) + per-b counts + bases
// Reference declares int64 labels; jax w/o x64 silently yields int32. An
// int64 buffer (values 0..7, little-endian) read as int32 is [v,0,v,0,...].
__global__ void k_labels(const int* __restrict__ lab32) {
    __shared__ int lab[NB];
    __shared__ int cnt[NB];
    __shared__ int is64s;
    int t = threadIdx.x;
    if (t == 0) {
        bool is64 = true;
        for (int i = 1; i < NB; i += 2) if (lab32[i] != 0) { is64 = false; break; }
        if (is64) for (int i = 0; i < NB; i += 2) {
            int v = lab32[i];
            if (v < 0 || v >= 8) { is64 = false; break; }
        }
        is64s = is64 ? 1 : 0;
    }
    __syncthreads();
    if (t < NB) {
        lab[t] = is64s ? (int)((const long long*)lab32)[t] : lab32[t];
    }
    __syncthreads();
    if (t < NB) {
        int same = 0;
        #pragma unroll 8
        for (int o = 0; o < NB; o++) same += (lab[o] == lab[t]) ? 1 : 0;
        g_nneg[t] = (float)((NB - same) * (NL - 1));
        cnt[t]    = same * (NL - 1);
        g_lab[t]  = lab[t];
    }
    __syncthreads();
    if (t == 0) {
        int s = 0;
        for (int b = 0; b < NB; b++) { g_base[b] = s; s += cnt[b]; }
        g_np = s;
    }
}

// ------------------------------------------------------------ 1: normalize
__global__ void k_norm(const float* __restrict__ x) {
    __shared__ float red[32];
    int r = blockIdx.x, d = threadIdx.x;
    float v = x[r * ND + d];
    float ss = blockReduceSum(v * v, red);
    float inv = 1.f / fmaxf(sqrtf(ss), 1e-12f);
    float xn = v * inv;
    int b = r / NL, p = r - b * NL;
    if (p == 0) g_anch[b * ND + d] = xn;
    else        g_toks[(b * (NL - 1) + p - 1) * ND + d] = xn;
}

// ----------------------------- 2: build compacted active-pair list (per b)
__global__ void k_plan(void) {
    __shared__ int lab[NB];
    __shared__ int wc[8];
    int b = blockIdx.x;
    int t = threadIdx.x, lane = t & 31, w = t >> 5;
    if (t < NB) lab[t] = g_lab[t];
    __syncthreads();
    int mb = lab[b];
    int base = g_base[b];
    #pragma unroll
    for (int q = 0; q < 3; q++) {
        int j = q * 256 + t;
        bool act = (lab[j >> 4] == mb);
        unsigned bal = __ballot_sync(0xffffffffu, act);
        if (lane == 0) wc[w] = __popc(bal);
        __syncthreads();
        int off = 0, tot = 0;
        #pragma unroll
        for (int i = 0; i < 8; i++) { int v = wc[i]; if (i < w) off += v; tot += v; }
        if (act) g_pairs[base + off + __popc(bal & ((1u << lane) - 1u))] = (b << 16) | j;
        base += tot;
        __syncthreads();
    }
}

// -------------------------- 3: anchor sims -> Ea = exp(s_anc), c = 1/sum_neg
__global__ void k_anchor(void) {
    int b = blockIdx.x, t = threadIdx.x;
    __shared__ float anc[ND];
    __shared__ int   lab[NB];
    __shared__ float red[32];
    anc[t] = g_anch[b * ND + t];
    if (t < NB) lab[t] = g_lab[t];
    __syncthreads();
    int mb = lab[b];

    float E[3]; float p = 0.f;
    const float4* an = (const float4*)anc;
    #pragma unroll
    for (int q = 0; q < 3; q++) {
        int k = t + q * 256;
        const float4* tk = (const float4*)(g_toks + k * ND);
        float dot = 0.f;
        #pragma unroll 8
        for (int d = 0; d < ND / 4; d++) {
            float4 a = an[d], v = tk[d];
            dot += a.x * v.x + a.y * v.y + a.z * v.z + a.w * v.w;
        }
        E[q] = expf(dot);          // T = 1
        if (lab[k >> 4] != mb) p += E[q];
    }
    float P = blockReduceSum(p, red);
    #pragma unroll
    for (int q = 0; q < 3; q++) g_Ea[b * NM + t + q * 256] = E[q];
    if (t == 0) g_c[b] = 1.f / P;
}

// -------------------------- 4a: split-K GEMM partials of toks @ toks^T
__global__ void k_gemm(void) {
    __shared__ float As[64][33];
    __shared__ float Bs[64][33];
    int tx = threadIdx.x & 15, ty = threadIdx.x >> 4;
    int jb = blockIdx.y * 64, kb = blockIdx.x * 64;
    int z  = blockIdx.z;
    float acc[4][4] = {};
    int kbeg = z * (ND / KSPLIT), kend = kbeg + ND / KSPLIT;
    for (int k0 = kbeg; k0 < kend; k0 += 32) {
        for (int i = threadIdx.x; i < 64 * 32; i += 256) {
            int r = i >> 5, c = i & 31;
            As[r][c] = g_toks[(jb + r) * ND + k0 + c];
            Bs[r][c] = g_toks[(kb + r) * ND + k0 + c];
        }
        __syncthreads();
        #pragma unroll
        for (int dd = 0; dd < 32; dd++) {
            float a0 = As[ty*4+0][dd], a1 = As[ty*4+1][dd],
                  a2 = As[ty*4+2][dd], a3 = As[ty*4+3][dd];
            float b0 = Bs[tx*4+0][dd], b1 = Bs[tx*4+1][dd],
                  b2 = Bs[tx*4+2][dd], b3 = Bs[tx*4+3][dd];
            acc[0][0] += a0*b0; acc[0][1] += a0*b1; acc[0][2] += a0*b2; acc[0][3] += a0*b3;
            acc[1][0] += a1*b0; acc[1][1] += a1*b1; acc[1][2] += a1*b2; acc[1][3] += a1*b3;
            acc[2][0] += a2*b0; acc[2][1] += a2*b1; acc[2][2] += a2*b2; acc[2][3] += a2*b3;
            acc[3][0] += a3*b0; acc[3][1] += a3*b1; acc[3][2] += a3*b2; acc[3][3] += a3*b3;
        }
        __syncthreads();
    }
    #pragma unroll
    for (int i = 0; i < 4; i++)
        #pragma unroll
        for (int l = 0; l < 4; l++)
            g_sp[z][(jb + ty*4 + i) * NM + kb + tx*4 + l] = acc[i][l];
}

// -------------------------- 4b: combine split-K partials, apply exp
__global__ void k_combine(void) {
    int i = blockIdx.x * 256 + threadIdx.x;      // float4 index, NM*NM/4 total
    const float4* p0 = (const float4*)g_sp[0];
    const float4* p1 = (const float4*)g_sp[1];
    const float4* p2 = (const float4*)g_sp[2];
    const float4* p3 = (const float4*)g_sp[3];
    float4 a = p0[i], b = p1[i], c = p2[i], d = p3[i];
    float4 r;
    r.x = expf((a.x + b.x) + (c.x + d.x));
    r.y = expf((a.y + b.y) + (c.y + d.y));
    r.z = expf((a.z + b.z) + (c.z + d.z));
    r.w = expf((a.w + b.w) + (c.w + d.w));
    ((float4*)g_Et)[i] = r;
}

// ------------------- 5: warp-per-pair symmetric KL (cancellation-free)
// e=c*Et, a=c*Ea, t=e-a, mu=exp(e)-1 (series), d=mu-nu=t*h (series)
// symKL = 0.5*(Sdt*D1 - Sd*N1)/(D1*D2); D1=n+Smu, N1=St+Smut, D2=D1-Sd
__global__ void k_pairs(void) {
    __shared__ int lab[NB];
    int t = threadIdx.x, lane = t & 31, w = t >> 5;
    if (t < NB) lab[t] = g_lab[t];
    __syncthreads();
    int np = g_np;
    for (int p = blockIdx.x * 8 + w; p < np; p += PAIR_BLOCKS * 8) {
        int pr = g_pairs[p];
        int b = pr >> 16, j = pr & 0xffff;
        int mb = lab[b];
        float c = g_c[b];
        const float* Et = g_Et + j * NM;
        const float* Ea = g_Ea + b * NM;

        float s0 = 0.f, s1 = 0.f, s2 = 0.f, s3 = 0.f, s4 = 0.f;
        #pragma unroll 4
        for (int i = 0; i < NM / 32; i++) {
            int k = i * 32 + lane;
            float m  = (lab[k >> 4] != mb) ? c : 0.f;   // zeroed lanes give 0 terms
            float e  = m * Et[k];
            float a  = m * Ea[k];
            float tt = e - a;
            float mu = e * (1.f + e * (0.5f + e * (1.f/6.f + e * (1.f/24.f))));
            float sp = e + a;
            float e2 = e * e, ea = e * a, a2 = a * a;
            float h  = 1.f + 0.5f * sp + (e2 + ea + a2) * (1.f/6.f)
                     + sp * (e2 + a2) * (1.f/24.f);
            float d  = tt * h;
            s0 += tt; s1 += mu; s2 = fmaf(mu, tt, s2);
            s3 += d;  s4 = fmaf(tt, d, s4);
        }
        #pragma unroll
        for (int o = 16; o > 0; o >>= 1) {
            s0 += __shfl_down_sync(0xffffffffu, s0, o);
            s1 += __shfl_down_sync(0xffffffffu, s1, o);
            s2 += __shfl_down_sync(0xffffffffu, s2, o);
            s3 += __shfl_down_sync(0xffffffffu, s3, o);
            s4 += __shfl_down_sync(0xffffffffu, s4, o);
        }
        if (lane == 0) {
            float n  = g_nneg[b];
            float D1 = n + s1;
            float N1 = s0 + s2;
            float D2 = D1 - s3;
            float num = s4 * D1 - s3 * N1;
            g_kl[b * NM + j] = 0.5f * num / (D1 * D2);
        }
    }
}

// ------------------------------------- 6a: per-b row mean (block per b)
__global__ void k_final1(void) {
    __shared__ int lab[NB];
    __shared__ float red[32];
    int b = blockIdx.x, t = threadIdx.x;
    if (t < NB) lab[t] = g_lab[t];
    __syncthreads();
    int mb = lab[b];
    float rs = 0.f, cnt = 0.f;
    #pragma unroll
    for (int q = 0; q < 3; q++) {
        int j = q * 256 + t;
        if (lab[j >> 4] == mb) { rs += g_kl[b * NM + j]; cnt += 1.f; }
    }
    float rowsum = blockReduceSum(rs, red);
    float P      = blockReduceSum(cnt, red);
    if (t == 0) g_row[b] = rowsum / P;
}

// ------------------------------------- 6b: deterministic 48-element reduce
__global__ void k_final2(float* __restrict__ out) {
    __shared__ float v[NB];
    int t = threadIdx.x;
    if (t < NB) v[t] = g_row[t];
    __syncthreads();
    if (t == 0) {
        float s = 0.f;
        for (int b = 0; b < NB; b++) s += v[b];
        out[0] = s / (float)NB;
    }
}

// ----------------------------------------------------------------- launch
extern "C" void kernel_launch(void* const* d_in, const int* in_sizes, int n_in,
                              void* d_out, int out_size) {
    const float* x     = (const float*)d_in[0];
    const int*   lab32 = (const int*)  d_in[1];
    float*       out   = (float*)      d_out;
    (void)in_sizes; (void)n_in; (void)out_size;

    k_labels <<<1, 64>>>(lab32);
    k_norm   <<<NB * NL, 256>>>(x);
    k_plan   <<<NB, 256>>>();
    k_anchor <<<NB, 256>>>();
    k_gemm   <<<dim3(NM / 64, NM / 64, KSPLIT), 256>>>();
    k_combine<<<NM * NM / 4 / 256, 256>>>();
    k_pairs  <<<PAIR_BLOCKS, 256>>>();
    k_final1 <<<NB, 256>>>();
    k_final2 <<<1, 64>>>(out);
}

// round 4
// speedup vs baseline: 2.0548x; 1.0997x over previous
#include <cuda_runtime.h>

#define NB 48
#define NL 17
#define ND 256
#define NM 768    /* NB*(NL-1) */
#define NR 832    /* NM + NB (anchors) padded to 64-row tiles */
#define KSPLIT 4
#define PAIR_BLOCKS 768

__device__ float g_all [NR*ND];         // rows 0..767 toks, 768..815 anchors, 816..831 zero
__device__ float g_sp  [KSPLIT][NR*NM]; // split-K partials of all @ toks^T
__device__ float g_E   [NR*NM];         // exp(sims): rows 0..767 = Et, 768..815 = Ea
__device__ float g_c   [NB];            // 1 / sum_neg exp(s_anc)
__device__ float g_kl  [NB*NM];
__device__ float g_row [NB];
__device__ float g_nneg[NB];
__device__ int   g_lab [NB];
__device__ int   g_base[NB];
__device__ int   g_np;
__device__ int   g_pairs[NB*NM];        // (b<<16)|j, grouped by b

// ---------------------------------------------------------------- utilities
__device__ __forceinline__ float blockReduceSum(float v, volatile float* sm) {
    int lane = threadIdx.x & 31, wid = threadIdx.x >> 5;
    #pragma unroll
    for (int o = 16; o > 0; o >>= 1) v += __shfl_down_sync(0xffffffffu, v, o);
    if (lane == 0) sm[wid] = v;
    __syncthreads();
    if (threadIdx.x < 32) {
        float r = (threadIdx.x < 8) ? sm[threadIdx.x] : 0.f;
        #pragma unroll
        for (int o = 4; o > 0; o >>= 1) r += __shfl_down_sync(0xffffffffu, r, o);
        if (threadIdx.x == 0) sm[0] = r;
    }
    __syncthreads();
    float r = sm[0];
    __syncthreads();
    return r;
}

// --------------------------- 0: labels (dtype sniff) + per-b counts + bases
// Reference declares int64 labels; jax w/o x64 silently yields int32. An
// int64 buffer (values 0..7, little-endian) read as int32 is [v,0,v,0,...].
__global__ void k_labels(const int* __restrict__ lab32) {
    __shared__ int lab[NB];
    __shared__ int cnt[NB];
    __shared__ int is64s;
    int t = threadIdx.x;
    if (t == 0) {
        bool is64 = true;
        for (int i = 1; i < NB; i += 2) if (lab32[i] != 0) { is64 = false; break; }
        if (is64) for (int i = 0; i < NB; i += 2) {
            int v = lab32[i];
            if (v < 0 || v >= 8) { is64 = false; break; }
        }
        is64s = is64 ? 1 : 0;
    }
    __syncthreads();
    if (t < NB) lab[t] = is64s ? (int)((const long long*)lab32)[t] : lab32[t];
    __syncthreads();
    if (t < NB) {
        int same = 0;
        #pragma unroll 8
        for (int o = 0; o < NB; o++) same += (lab[o] == lab[t]) ? 1 : 0;
        g_nneg[t] = (float)((NB - same) * (NL - 1));
        cnt[t]    = same * (NL - 1);
        g_lab[t]  = lab[t];
    }
    __syncthreads();
    if (t == 0) {
        int s = 0;
        for (int b = 0; b < NB; b++) { g_base[b] = s; s += cnt[b]; }
        g_np = s;
    }
}

// ----------------------------- 1: build compacted active-pair list (per b)
__global__ void k_plan(void) {
    __shared__ int lab[NB];
    __shared__ int wc[8];
    int b = blockIdx.x;
    int t = threadIdx.x, lane = t & 31, w = t >> 5;
    if (t < NB) lab[t] = g_lab[t];
    __syncthreads();
    int mb = lab[b];
    int base = g_base[b];
    #pragma unroll
    for (int q = 0; q < 3; q++) {
        int j = q * 256 + t;
        bool act = (lab[j >> 4] == mb);
        unsigned bal = __ballot_sync(0xffffffffu, act);
        if (lane == 0) wc[w] = __popc(bal);
        __syncthreads();
        int off = 0, tot = 0;
        #pragma unroll
        for (int i = 0; i < 8; i++) { int v = wc[i]; if (i < w) off += v; tot += v; }
        if (act) g_pairs[base + off + __popc(bal & ((1u << lane) - 1u))] = (b << 16) | j;
        base += tot;
        __syncthreads();
    }
}

// --------------------------------------- 2: normalize rows into g_all
// input row r (0..815): b=r/17, p=r%17; p==0 -> anchor row 768+b, else tok.
// blocks 816..831 zero the pad rows.
__global__ void k_norm(const float* __restrict__ x) {
    __shared__ float red[32];
    int r = blockIdx.x, d = threadIdx.x;
    if (r >= NB * NL) {                 // pad rows
        g_all[(NM + r - NB * NL + NB) * ND + d] = 0.f;  // rows 816..831
        return;
    }
    float v = x[r * ND + d];
    float ss = blockReduceSum(v * v, red);
    float inv = 1.f / fmaxf(sqrtf(ss), 1e-12f);
    float xn = v * inv;
    int b = r / NL, p = r - b * NL;
    int row = (p == 0) ? (NM + b) : (b * (NL - 1) + p - 1);
    g_all[row * ND + d] = xn;
}

// -------------------------- 3a: split-K GEMM partials of all @ toks^T
__global__ void k_gemm(void) {
    __shared__ float As[64][33];
    __shared__ float Bs[64][33];
    int tx = threadIdx.x & 15, ty = threadIdx.x >> 4;
    int jb = blockIdx.y * 64, kb = blockIdx.x * 64;   // jb: 0..768 (13), kb: 0..704 (12)
    int z  = blockIdx.z;
    float acc[4][4] = {};
    int kbeg = z * (ND / KSPLIT), kend = kbeg + ND / KSPLIT;
    for (int k0 = kbeg; k0 < kend; k0 += 32) {
        for (int i = threadIdx.x; i < 64 * 32; i += 256) {
            int r = i >> 5, c = i & 31;
            As[r][c] = g_all[(jb + r) * ND + k0 + c];
            Bs[r][c] = g_all[(kb + r) * ND + k0 + c];
        }
        __syncthreads();
        #pragma unroll
        for (int dd = 0; dd < 32; dd++) {
            float a0 = As[ty*4+0][dd], a1 = As[ty*4+1][dd],
                  a2 = As[ty*4+2][dd], a3 = As[ty*4+3][dd];
            float b0 = Bs[tx*4+0][dd], b1 = Bs[tx*4+1][dd],
                  b2 = Bs[tx*4+2][dd], b3 = Bs[tx*4+3][dd];
            acc[0][0] += a0*b0; acc[0][1] += a0*b1; acc[0][2] += a0*b2; acc[0][3] += a0*b3;
            acc[1][0] += a1*b0; acc[1][1] += a1*b1; acc[1][2] += a1*b2; acc[1][3] += a1*b3;
            acc[2][0] += a2*b0; acc[2][1] += a2*b1; acc[2][2] += a2*b2; acc[2][3] += a2*b3;
            acc[3][0] += a3*b0; acc[3][1] += a3*b1; acc[3][2] += a3*b2; acc[3][3] += a3*b3;
        }
        __syncthreads();
    }
    #pragma unroll
    for (int i = 0; i < 4; i++)
        #pragma unroll
        for (int l = 0; l < 4; l++)
            g_sp[z][(jb + ty*4 + i) * NM + kb + tx*4 + l] = acc[i][l];
}

// -------------------------- 3b: combine split-K partials, apply exp
__global__ void k_combine(void) {
    int i = blockIdx.x * 256 + threadIdx.x;      // float4 index over NR*NM/4
    const float4* p0 = (const float4*)g_sp[0];
    const float4* p1 = (const float4*)g_sp[1];
    const float4* p2 = (const float4*)g_sp[2];
    const float4* p3 = (const float4*)g_sp[3];
    float4 a = p0[i], b = p1[i], c = p2[i], d = p3[i];
    float4 r;
    r.x = expf((a.x + b.x) + (c.x + d.x));
    r.y = expf((a.y + b.y) + (c.y + d.y));
    r.z = expf((a.z + b.z) + (c.z + d.z));
    r.w = expf((a.w + b.w) + (c.w + d.w));
    ((float4*)g_E)[i] = r;
}

// -------------------------- 3c: c[b] = 1 / sum_neg Ea[b,k]
__global__ void k_c(void) {
    __shared__ int lab[NB];
    __shared__ float red[32];
    int b = blockIdx.x, t = threadIdx.x;
    if (t < NB) lab[t] = g_lab[t];
    __syncthreads();
    int mb = lab[b];
    const float* Ea = g_E + (NM + b) * NM;
    float p = 0.f;
    #pragma unroll
    for (int q = 0; q < 3; q++) {
        int k = q * 256 + t;
        if (lab[k >> 4] != mb) p += Ea[k];
    }
    float P = blockReduceSum(p, red);
    if (t == 0) g_c[b] = 1.f / P;
}

// ------------------- 4: warp-per-pair symmetric KL (cancellation-free)
// e=c*Et, a=c*Ea, t=e-a, mu=exp(e)-1 (series), d=mu-nu=t*h (series)
// symKL = 0.5*(Sdt*D1 - Sd*N1)/(D1*D2); D1=n+Smu, N1=St+Smut, D2=D1-Sd
__global__ void k_pairs(void) {
    __shared__ int lab[NB];
    int t = threadIdx.x, lane = t & 31, w = t >> 5;
    if (t < NB) lab[t] = g_lab[t];
    __syncthreads();
    int np = g_np;
    for (int p = blockIdx.x * 8 + w; p < np; p += PAIR_BLOCKS * 8) {
        int pr = g_pairs[p];
        int b = pr >> 16, j = pr & 0xffff;
        int mb = lab[b];
        float c = g_c[b];
        const float* Et = g_E + j * NM;
        const float* Ea = g_E + (NM + b) * NM;

        float s0 = 0.f, s1 = 0.f, s2 = 0.f, s3 = 0.f, s4 = 0.f;
        #pragma unroll 4
        for (int i = 0; i < NM / 32; i++) {
            int k = i * 32 + lane;
            float m  = (lab[k >> 4] != mb) ? c : 0.f;   // zeroed lanes give 0 terms
            float e  = m * Et[k];
            float a  = m * Ea[k];
            float tt = e - a;
            float mu = e * (1.f + e * (0.5f + e * (1.f/6.f + e * (1.f/24.f))));
            float sp = e + a;
            float e2 = e * e, ea = e * a, a2 = a * a;
            float h  = 1.f + 0.5f * sp + (e2 + ea + a2) * (1.f/6.f)
                     + sp * (e2 + a2) * (1.f/24.f);
            float d  = tt * h;
            s0 += tt; s1 += mu; s2 = fmaf(mu, tt, s2);
            s3 += d;  s4 = fmaf(tt, d, s4);
        }
        #pragma unroll
        for (int o = 16; o > 0; o >>= 1) {
            s0 += __shfl_down_sync(0xffffffffu, s0, o);
            s1 += __shfl_down_sync(0xffffffffu, s1, o);
            s2 += __shfl_down_sync(0xffffffffu, s2, o);
            s3 += __shfl_down_sync(0xffffffffu, s3, o);
            s4 += __shfl_down_sync(0xffffffffu, s4, o);
        }
        if (lane == 0) {
            float n  = g_nneg[b];
            float D1 = n + s1;
            float N1 = s0 + s2;
            float D2 = D1 - s3;
            float num = s4 * D1 - s3 * N1;
            g_kl[b * NM + j] = 0.5f * num / (D1 * D2);
        }
    }
}

// ------------------------------------- 5a: per-b row mean (block per b)
__global__ void k_final1(void) {
    __shared__ int lab[NB];
    __shared__ float red[32];
    int b = blockIdx.x, t = threadIdx.x;
    if (t < NB) lab[t] = g_lab[t];
    __syncthreads();
    int mb = lab[b];
    float rs = 0.f, cnt = 0.f;
    #pragma unroll
    for (int q = 0; q < 3; q++) {
        int j = q * 256 + t;
        if (lab[j >> 4] == mb) { rs += g_kl[b * NM + j]; cnt += 1.f; }
    }
    float rowsum = blockReduceSum(rs, red);
    float P      = blockReduceSum(cnt, red);
    if (t == 0) g_row[b] = rowsum / P;
}

// ------------------------------------- 5b: deterministic 48-element reduce
__global__ void k_final2(float* __restrict__ out) {
    __shared__ float v[NB];
    int t = threadIdx.x;
    if (t < NB) v[t] = g_row[t];
    __syncthreads();
    if (t == 0) {
        float s = 0.f;
        for (int b = 0; b < NB; b++) s += v[b];
        out[0] = s / (float)NB;
    }
}

// ----------------------------------------------------------------- launch
extern "C" void kernel_launch(void* const* d_in, const int* in_sizes, int n_in,
                              void* d_out, int out_size) {
    const float* x     = (const float*)d_in[0];
    const int*   lab32 = (const int*)  d_in[1];
    float*       out   = (float*)      d_out;
    (void)in_sizes; (void)n_in; (void)out_size;

    k_labels <<<1, 64>>>(lab32);
    k_plan   <<<NB, 256>>>();
    k_norm   <<<NR, 256>>>(x);
    k_gemm   <<<dim3(NM / 64, NR / 64, KSPLIT), 256>>>();
    k_combine<<<NR * NM / 4 / 256, 256>>>();
    k_c      <<<NB, 256>>>();
    k_pairs  <<<PAIR_BLOCKS, 256>>>();
    k_final1 <<<NB, 256>>>();
    k_final2 <<<1, 64>>>(out);
}